// round 2
// baseline (speedup 1.0000x reference)
#include <cuda_runtime.h>
#include <math.h>

#define B_ 2
#define T_ 2048
#define DIM_ 2048
#define H_ 16
#define HD_ 128

// Scratch (alloc-free rules: __device__ globals)
static __device__ float g_q[(size_t)B_ * T_ * DIM_];     // Q after GEMM+RoPE, [B,T,H,HD]
static __device__ float g_attn[(size_t)B_ * T_ * DIM_];  // attention out, [B,T,DIM]

// ---------------------------------------------------------------------------
// SGEMM: C[M,N] = A[M,K] @ B[K,N], 128x128 block tile, BK=16, 8x8 per thread.
// asel==1 -> A = g_attn ; csel==1 -> C = g_q  (scratch selection w/o symbol API)
// ---------------------------------------------------------------------------
__global__ __launch_bounds__(256) void sgemm128(
    const float* __restrict__ A, const float* __restrict__ Bm, float* __restrict__ C,
    int M, int N, int K, int asel, int csel)
{
    if (asel == 1) A = g_attn;
    if (csel == 1) C = g_q;

    __shared__ float As[16][128];   // transposed: As[k][m]
    __shared__ float Bs[16][128];   // Bs[k][n]

    int tid = threadIdx.x;
    int tx = tid & 15, ty = tid >> 4;
    int bn0 = blockIdx.x * 128, bm0 = blockIdx.y * 128;

    float acc[8][8];
#pragma unroll
    for (int i = 0; i < 8; i++)
#pragma unroll
        for (int j = 0; j < 8; j++) acc[i][j] = 0.f;

    int ar = tid >> 2, ac = (tid & 3) << 2;     // A: 64 rows/pass x 4 k-groups
    int br = tid >> 5, bc = (tid & 31) << 2;    // B: 8 rows/pass x 32 col-groups

    const float* Aptr = A + (size_t)(bm0 + ar) * K + ac;
    const float* Bptr = Bm + (size_t)br * N + bn0 + bc;

    for (int k0 = 0; k0 < K; k0 += 16) {
        float4 a0 = *(const float4*)(Aptr);
        float4 a1 = *(const float4*)(Aptr + (size_t)64 * K);
        float4 b0 = *(const float4*)(Bptr);
        float4 b1 = *(const float4*)(Bptr + (size_t)8 * N);

        As[ac + 0][ar] = a0.x; As[ac + 1][ar] = a0.y;
        As[ac + 2][ar] = a0.z; As[ac + 3][ar] = a0.w;
        As[ac + 0][ar + 64] = a1.x; As[ac + 1][ar + 64] = a1.y;
        As[ac + 2][ar + 64] = a1.z; As[ac + 3][ar + 64] = a1.w;
        *(float4*)&Bs[br][bc] = b0;
        *(float4*)&Bs[br + 8][bc] = b1;
        __syncthreads();

#pragma unroll
        for (int kk = 0; kk < 16; kk++) {
            float a[8], b[8];
            *(float4*)(a)     = *(const float4*)&As[kk][ty * 8];
            *(float4*)(a + 4) = *(const float4*)&As[kk][ty * 8 + 4];
            *(float4*)(b)     = *(const float4*)&Bs[kk][tx * 8];
            *(float4*)(b + 4) = *(const float4*)&Bs[kk][tx * 8 + 4];
#pragma unroll
            for (int i = 0; i < 8; i++)
#pragma unroll
                for (int j = 0; j < 8; j++)
                    acc[i][j] = fmaf(a[i], b[j], acc[i][j]);
        }
        __syncthreads();
        Aptr += 16;
        Bptr += (size_t)16 * N;
    }

#pragma unroll
    for (int i = 0; i < 8; i++) {
        float* cp = C + (size_t)(bm0 + ty * 8 + i) * N + bn0 + tx * 8;
        *(float4*)cp       = make_float4(acc[i][0], acc[i][1], acc[i][2], acc[i][3]);
        *(float4*)(cp + 4) = make_float4(acc[i][4], acc[i][5], acc[i][6], acc[i][7]);
    }
}

// ---------------------------------------------------------------------------
// RoPE (in place). out[j] = x[j]*cos - x[j+64]*sin ; out[j+64] = x[j+64]*cos + x[j]*sin
// ---------------------------------------------------------------------------
__global__ __launch_bounds__(256) void rope_q_kernel()
{
    int idx = blockIdx.x * 256 + threadIdx.x;      // < B*T*H*64
    int j = idx & 63;
    int h = (idx >> 6) & (H_ - 1);
    int t = (idx >> 10) & (T_ - 1);
    int b = idx >> 21;
    float inv = powf(10000.0f, -(float)j * (1.0f / 64.0f));
    float ang = (float)t * inv;
    float sv, cv;
    sincosf(ang, &sv, &cv);
    size_t base = (((size_t)b * T_ + t) * H_ + h) * (size_t)HD_;
    float x1 = g_q[base + j], x2 = g_q[base + j + 64];
    g_q[base + j]      = x1 * cv - x2 * sv;
    g_q[base + j + 64] = x2 * cv + x1 * sv;
}

__global__ __launch_bounds__(256) void rope_k_kernel(float* __restrict__ kb)
{
    int idx = blockIdx.x * 256 + threadIdx.x;      // < B*T*64
    int j = idx & 63;
    int t = (idx >> 6) & (T_ - 1);
    int b = idx >> 17;
    float inv = powf(10000.0f, -(float)j * (1.0f / 64.0f));
    float ang = (float)t * inv;
    float sv, cv;
    sincosf(ang, &sv, &cv);
    size_t base = ((size_t)b * T_ + t) * (size_t)HD_;
    float x1 = kb[base + j], x2 = kb[base + j + 64];
    kb[base + j]      = x1 * cv - x2 * sv;
    kb[base + j + 64] = x2 * cv + x1 * sv;
}

// ---------------------------------------------------------------------------
// Flash attention, fp32, BQ=BKV=64, online softmax, causal.
// Q/K stored transposed [d][row] (stride 68: float4-aligned, bank-safe frags).
// grid: (T/64, B*H), 256 threads.
// ---------------------------------------------------------------------------
#define BQ 64
#define BKV 64
#define TSTR 68     // transposed-tile row stride (64 + 4 pad)
#define PSTR 68     // P tile stride
#define MSTR 17     // partial max/sum stride

__global__ __launch_bounds__(256) void flash_attn(
    const float* __restrict__ kbuf, const float* __restrict__ vbuf)
{
    extern __shared__ float sm[];
    float* Qs   = sm;                    // [HD][TSTR]
    float* Ks   = Qs + HD_ * TSTR;       // [HD][TSTR]
    float* Vs   = Ks + HD_ * TSTR;       // [BKV][HD]
    float* Ps   = Vs + BKV * HD_;        // [BQ][PSTR]
    float* pmax = Ps + BQ * PSTR;        // [BQ][MSTR]
    float* psum = pmax + BQ * MSTR;      // [BQ][MSTR]
    float* rowm = psum + BQ * MSTR;      // [BQ]
    float* rowl = rowm + BQ;
    float* rowa = rowl + BQ;

    int tid = threadIdx.x;
    int tx = tid & 15, ty = tid >> 4;
    int qb = blockIdx.x;
    int bh = (int)blockIdx.y;
    int b = bh >> 4, h = bh & 15;
    int q0 = qb * BQ;
    const float scale = 0.08838834764831845f;   // 1/sqrt(128)

    if (tid < BQ) { rowm[tid] = -INFINITY; rowl[tid] = 0.f; }

    // Load Q tile (scaled) into transposed smem
    {
        int r = tid >> 5;
        int d4 = (tid & 31) << 2;
        const float* qp = g_q + (((size_t)b * T_ + q0) * H_ + h) * (size_t)HD_;
#pragma unroll
        for (int it = 0; it < 8; it++, r += 8) {
            float4 v = *(const float4*)(qp + (size_t)r * DIM_ + d4);
            float vv[4] = {v.x * scale, v.y * scale, v.z * scale, v.w * scale};
#pragma unroll
            for (int cc = 0; cc < 4; cc++) {
                int c = (cc + tid) & 3;   // stagger stores to reduce bank conflicts
                Qs[(d4 + c) * TSTR + r] = vv[c];
            }
        }
    }

    float O[4][8];
#pragma unroll
    for (int i = 0; i < 4; i++)
#pragma unroll
        for (int j = 0; j < 8; j++) O[i][j] = 0.f;

    const float* kb_base = kbuf + (size_t)b * T_ * HD_;
    const float* vb_base = vbuf + (size_t)b * T_ * HD_;

    for (int kb = 0; kb <= qb; kb++) {
        int k0 = kb * BKV;
        __syncthreads();    // previous iter's phase2 reads done; also orders Q stores
        {
            int r = tid >> 5;
            int d4 = (tid & 31) << 2;
#pragma unroll
            for (int it = 0; it < 8; it++, r += 8) {
                float4 kv = *(const float4*)(kb_base + (size_t)(k0 + r) * HD_ + d4);
                float kk[4] = {kv.x, kv.y, kv.z, kv.w};
#pragma unroll
                for (int cc = 0; cc < 4; cc++) {
                    int c = (cc + tid) & 3;
                    Ks[(d4 + c) * TSTR + r] = kk[c];
                }
                float4 vv = *(const float4*)(vb_base + (size_t)(k0 + r) * HD_ + d4);
                *(float4*)&Vs[r * HD_ + d4] = vv;
            }
        }
        __syncthreads();

        // Phase 1: S(4x4 per thread) = Q @ K^T  (rows ty*4.., cols tx*4..)
        float s[4][4];
#pragma unroll
        for (int i = 0; i < 4; i++)
#pragma unroll
            for (int j = 0; j < 4; j++) s[i][j] = 0.f;

#pragma unroll 4
        for (int d = 0; d < HD_; d++) {
            float4 a  = *(const float4*)&Qs[d * TSTR + ty * 4];
            float4 bb = *(const float4*)&Ks[d * TSTR + tx * 4];
            float av[4] = {a.x, a.y, a.z, a.w};
            float bv[4] = {bb.x, bb.y, bb.z, bb.w};
#pragma unroll
            for (int i = 0; i < 4; i++)
#pragma unroll
                for (int j = 0; j < 4; j++)
                    s[i][j] = fmaf(av[i], bv[j], s[i][j]);
        }

        if (kb == qb) {   // causal mask on the diagonal tile
#pragma unroll
            for (int i = 0; i < 4; i++)
#pragma unroll
                for (int j = 0; j < 4; j++)
                    if (ty * 4 + i < tx * 4 + j) s[i][j] = -1e30f;
        }

        // Stage A: per-thread partial row max
#pragma unroll
        for (int i = 0; i < 4; i++) {
            float mx = fmaxf(fmaxf(s[i][0], s[i][1]), fmaxf(s[i][2], s[i][3]));
            pmax[(ty * 4 + i) * MSTR + tx] = mx;
        }
        __syncthreads();

        // Stage B: reduce row max, update running max + alpha
        if (tid < BQ) {
            float mt = -INFINITY;
#pragma unroll
            for (int t = 0; t < 16; t++) mt = fmaxf(mt, pmax[tid * MSTR + t]);
            float mo = rowm[tid];
            float mn = fmaxf(mo, mt);
            rowm[tid] = mn;
            rowa[tid] = __expf(mo - mn);
        }
        __syncthreads();

        // Stage C: exponentiate, write P, partial row sums
#pragma unroll
        for (int i = 0; i < 4; i++) {
            float mn = rowm[ty * 4 + i];
            float p0 = __expf(s[i][0] - mn);
            float p1 = __expf(s[i][1] - mn);
            float p2 = __expf(s[i][2] - mn);
            float p3 = __expf(s[i][3] - mn);
            *(float4*)&Ps[(ty * 4 + i) * PSTR + tx * 4] = make_float4(p0, p1, p2, p3);
            psum[(ty * 4 + i) * MSTR + tx] = p0 + p1 + p2 + p3;
        }
        __syncthreads();

        // Stage D: update running denominator (runs concurrently with phase 2)
        if (tid < BQ) {
            float sum = 0.f;
#pragma unroll
            for (int t = 0; t < 16; t++) sum += psum[tid * MSTR + t];
            rowl[tid] = rowl[tid] * rowa[tid] + sum;
        }

        // Phase 2: O = O*alpha + P @ V   (rows ty*4.., cols tx*8..)
#pragma unroll
        for (int i = 0; i < 4; i++) {
            float al = rowa[ty * 4 + i];
#pragma unroll
            for (int j = 0; j < 8; j++) O[i][j] *= al;
        }
#pragma unroll 2
        for (int k = 0; k < BKV; k++) {
            float p[4];
#pragma unroll
            for (int i = 0; i < 4; i++) p[i] = Ps[(ty * 4 + i) * PSTR + k];
            float4 v0 = *(const float4*)&Vs[k * HD_ + tx * 8];
            float4 v1 = *(const float4*)&Vs[k * HD_ + tx * 8 + 4];
            float vv[8] = {v0.x, v0.y, v0.z, v0.w, v1.x, v1.y, v1.z, v1.w};
#pragma unroll
            for (int i = 0; i < 4; i++)
#pragma unroll
                for (int j = 0; j < 8; j++)
                    O[i][j] = fmaf(p[i], vv[j], O[i][j]);
        }
    }
    __syncthreads();

    // Finalize: divide by l, write [B,T,H,HD]
#pragma unroll
    for (int i = 0; i < 4; i++) {
        float inv = 1.f / rowl[ty * 4 + i];
        float* op = g_attn + (((size_t)b * T_ + q0 + ty * 4 + i) * H_ + h) * (size_t)HD_ + tx * 8;
        *(float4*)op       = make_float4(O[i][0] * inv, O[i][1] * inv, O[i][2] * inv, O[i][3] * inv);
        *(float4*)(op + 4) = make_float4(O[i][4] * inv, O[i][5] * inv, O[i][6] * inv, O[i][7] * inv);
    }
}

static const int FLASH_SMEM = (HD_ * TSTR * 2 + BKV * HD_ + BQ * PSTR + BQ * MSTR * 2 + 3 * BQ) * 4;

// ---------------------------------------------------------------------------
extern "C" void kernel_launch(void* const* d_in, const int* in_sizes, int n_in,
                              void* d_out, int out_size)
{
    const float* x  = (const float*)d_in[0];
    const float* Wq = (const float*)d_in[1];
    const float* Wk = (const float*)d_in[2];
    const float* Wv = (const float*)d_in[3];
    const float* Wo = (const float*)d_in[4];

    float* out = (float*)d_out;                       // [B,T,DIM]
    float* pk  = out + (size_t)B_ * T_ * DIM_;        // present_k [B,1,T,HD]
    float* pv  = pk + (size_t)B_ * T_ * HD_;          // present_v [B,1,T,HD]

    cudaFuncSetAttribute(flash_attn, cudaFuncAttributeMaxDynamicSharedMemorySize, FLASH_SMEM);

    dim3 blk(256);
    // Q = x @ Wq  -> g_q
    sgemm128<<<dim3(DIM_ / 128, (B_ * T_) / 128), blk>>>(x, Wq, nullptr, B_ * T_, DIM_, DIM_, 0, 1);
    // K = x @ Wk -> present_k ; V = x @ Wv -> present_v
    sgemm128<<<dim3(1, (B_ * T_) / 128), blk>>>(x, Wk, pk, B_ * T_, HD_, DIM_, 0, 0);
    sgemm128<<<dim3(1, (B_ * T_) / 128), blk>>>(x, Wv, pv, B_ * T_, HD_, DIM_, 0, 0);
    // RoPE in place
    rope_q_kernel<<<(B_ * T_ * H_ * 64) / 256, blk>>>();
    rope_k_kernel<<<(B_ * T_ * 64) / 256, blk>>>(pk);
    // Attention -> g_attn
    flash_attn<<<dim3(T_ / BQ, B_ * H_), blk, FLASH_SMEM>>>(pk, pv);
    // out = attn @ Wo
    sgemm128<<<dim3(DIM_ / 128, (B_ * T_) / 128), blk>>>(nullptr, Wo, out, B_ * T_, DIM_, DIM_, 1, 0);
}

// round 3
// speedup vs baseline: 1.5469x; 1.5469x over previous
#include <cuda_runtime.h>
#include <math.h>
#include <stdint.h>

#define B_ 2
#define T_ 2048
#define DIM_ 2048
#define H_ 16
#define HD_ 128

// Scratch (alloc-free rules: __device__ globals)
static __device__ float g_q[(size_t)B_ * T_ * DIM_];     // Q after GEMM+RoPE, [B,T,H,HD]
static __device__ float g_attn[(size_t)B_ * T_ * DIM_];  // attention out, [B,T,DIM]

// ---------------------------------------------------------------------------
// TF32 helpers
// ---------------------------------------------------------------------------
__device__ __forceinline__ uint32_t f2tf(float x) {
    uint32_t r;
    asm("cvt.rna.tf32.f32 %0, %1;" : "=r"(r) : "f"(x));
    return r;
}

__device__ __forceinline__ void mma8(float* c, uint32_t a0, uint32_t a1, uint32_t a2,
                                     uint32_t a3, uint32_t b0, uint32_t b1) {
    asm volatile(
        "mma.sync.aligned.m16n8k8.row.col.f32.tf32.tf32.f32 "
        "{%0,%1,%2,%3},{%4,%5,%6,%7},{%8,%9},{%0,%1,%2,%3};"
        : "+f"(c[0]), "+f"(c[1]), "+f"(c[2]), "+f"(c[3])
        : "r"(a0), "r"(a1), "r"(a2), "r"(a3), "r"(b0), "r"(b1));
}

// ---------------------------------------------------------------------------
// TF32 tensor-core GEMM: C[M,N] = A[M,K] @ B[K,N]
// 128x128 block tile, BK=16, 256 threads = 8 warps in 2(M) x 4(N), warp 64x32.
// Per warp: 4x4 grid of m16n8k8 mma. asel==1 -> A=g_attn ; csel==1 -> C=g_q.
// ---------------------------------------------------------------------------
__global__ __launch_bounds__(256) void tgemm(
    const float* __restrict__ A, const float* __restrict__ Bm, float* __restrict__ C,
    int M, int N, int K, int asel, int csel)
{
    if (asel == 1) A = g_attn;
    if (csel == 1) C = g_q;

    __shared__ uint32_t As[16][136];   // [k][m], tf32 bits; stride 136 -> conflict-free frag reads
    __shared__ uint32_t Bs[16][136];   // [k][n]

    int tid = threadIdx.x;
    int bn0 = blockIdx.x * 128, bm0 = blockIdx.y * 128;
    int warp = tid >> 5, lane = tid & 31;
    int wm = (warp & 1) * 64, wn = (warp >> 1) * 32;
    int lr = lane >> 2, lc = lane & 3;

    float acc[4][4][4];
#pragma unroll
    for (int mt = 0; mt < 4; mt++)
#pragma unroll
        for (int nt = 0; nt < 4; nt++)
#pragma unroll
            for (int i = 0; i < 4; i++) acc[mt][nt][i] = 0.f;

    int ar = tid >> 2, ac = (tid & 3) << 2;     // A: rows ar, ar+64; k cols ac..ac+3
    int br = tid >> 5, bc = (tid & 31) << 2;    // B: k rows br, br+8; n cols bc..bc+3

    const float* Ap = A + (size_t)(bm0 + ar) * K + ac;
    const float* Bp = Bm + (size_t)br * N + bn0 + bc;

    for (int k0 = 0; k0 < K; k0 += 16) {
        float4 a0v = *(const float4*)(Ap);
        float4 a1v = *(const float4*)(Ap + (size_t)64 * K);
        float4 b0v = *(const float4*)(Bp);
        float4 b1v = *(const float4*)(Bp + (size_t)8 * N);
        __syncthreads();   // previous compute done before overwriting tiles

        As[ac + 0][ar] = f2tf(a0v.x); As[ac + 1][ar] = f2tf(a0v.y);
        As[ac + 2][ar] = f2tf(a0v.z); As[ac + 3][ar] = f2tf(a0v.w);
        As[ac + 0][ar + 64] = f2tf(a1v.x); As[ac + 1][ar + 64] = f2tf(a1v.y);
        As[ac + 2][ar + 64] = f2tf(a1v.z); As[ac + 3][ar + 64] = f2tf(a1v.w);
        *(uint4*)&Bs[br][bc]     = make_uint4(f2tf(b0v.x), f2tf(b0v.y), f2tf(b0v.z), f2tf(b0v.w));
        *(uint4*)&Bs[br + 8][bc] = make_uint4(f2tf(b1v.x), f2tf(b1v.y), f2tf(b1v.z), f2tf(b1v.w));
        __syncthreads();

#pragma unroll
        for (int kk = 0; kk < 16; kk += 8) {
            uint32_t bf[4][2];
#pragma unroll
            for (int nt = 0; nt < 4; nt++) {
                bf[nt][0] = Bs[kk + lc][wn + nt * 8 + lr];
                bf[nt][1] = Bs[kk + lc + 4][wn + nt * 8 + lr];
            }
#pragma unroll
            for (int mt = 0; mt < 4; mt++) {
                uint32_t a0 = As[kk + lc][wm + mt * 16 + lr];
                uint32_t a1 = As[kk + lc][wm + mt * 16 + lr + 8];
                uint32_t a2 = As[kk + lc + 4][wm + mt * 16 + lr];
                uint32_t a3 = As[kk + lc + 4][wm + mt * 16 + lr + 8];
#pragma unroll
                for (int nt = 0; nt < 4; nt++)
                    mma8(acc[mt][nt], a0, a1, a2, a3, bf[nt][0], bf[nt][1]);
            }
        }
        Ap += 16;
        Bp += (size_t)16 * N;
    }

#pragma unroll
    for (int mt = 0; mt < 4; mt++) {
        int row = bm0 + wm + mt * 16 + lr;
#pragma unroll
        for (int nt = 0; nt < 4; nt++) {
            int col = bn0 + wn + nt * 8 + lc * 2;
            *(float2*)&C[(size_t)row * N + col]       = make_float2(acc[mt][nt][0], acc[mt][nt][1]);
            *(float2*)&C[(size_t)(row + 8) * N + col] = make_float2(acc[mt][nt][2], acc[mt][nt][3]);
        }
    }
}

// ---------------------------------------------------------------------------
// RoPE (in place)
// ---------------------------------------------------------------------------
__global__ __launch_bounds__(256) void rope_q_kernel()
{
    int idx = blockIdx.x * 256 + threadIdx.x;      // < B*T*H*64
    int j = idx & 63;
    int h = (idx >> 6) & (H_ - 1);
    int t = (idx >> 10) & (T_ - 1);
    int b = idx >> 21;
    float inv = powf(10000.0f, -(float)j * (1.0f / 64.0f));
    float ang = (float)t * inv;
    float sv, cv;
    sincosf(ang, &sv, &cv);
    size_t base = (((size_t)b * T_ + t) * H_ + h) * (size_t)HD_;
    float x1 = g_q[base + j], x2 = g_q[base + j + 64];
    g_q[base + j]      = x1 * cv - x2 * sv;
    g_q[base + j + 64] = x2 * cv + x1 * sv;
}

__global__ __launch_bounds__(256) void rope_k_kernel(float* __restrict__ kb)
{
    int idx = blockIdx.x * 256 + threadIdx.x;      // < B*T*64
    int j = idx & 63;
    int t = (idx >> 6) & (T_ - 1);
    int b = idx >> 17;
    float inv = powf(10000.0f, -(float)j * (1.0f / 64.0f));
    float ang = (float)t * inv;
    float sv, cv;
    sincosf(ang, &sv, &cv);
    size_t base = ((size_t)b * T_ + t) * (size_t)HD_;
    float x1 = kb[base + j], x2 = kb[base + j + 64];
    kb[base + j]      = x1 * cv - x2 * sv;
    kb[base + j + 64] = x2 * cv + x1 * sv;
}

// ---------------------------------------------------------------------------
// Flash attention, fp32, BQ=BKV=64, online softmax, causal. (unchanged)
// ---------------------------------------------------------------------------
#define BQ 64
#define BKV 64
#define TSTR 68
#define PSTR 68
#define MSTR 17

__global__ __launch_bounds__(256) void flash_attn(
    const float* __restrict__ kbuf, const float* __restrict__ vbuf)
{
    extern __shared__ float sm[];
    float* Qs   = sm;                    // [HD][TSTR]
    float* Ks   = Qs + HD_ * TSTR;       // [HD][TSTR]
    float* Vs   = Ks + HD_ * TSTR;       // [BKV][HD]
    float* Ps   = Vs + BKV * HD_;        // [BQ][PSTR]
    float* pmax = Ps + BQ * PSTR;        // [BQ][MSTR]
    float* psum = pmax + BQ * MSTR;      // [BQ][MSTR]
    float* rowm = psum + BQ * MSTR;      // [BQ]
    float* rowl = rowm + BQ;
    float* rowa = rowl + BQ;

    int tid = threadIdx.x;
    int tx = tid & 15, ty = tid >> 4;
    int qb = blockIdx.x;
    int bh = (int)blockIdx.y;
    int b = bh >> 4, h = bh & 15;
    int q0 = qb * BQ;
    const float scale = 0.08838834764831845f;

    if (tid < BQ) { rowm[tid] = -INFINITY; rowl[tid] = 0.f; }

    {
        int r = tid >> 5;
        int d4 = (tid & 31) << 2;
        const float* qp = g_q + (((size_t)b * T_ + q0) * H_ + h) * (size_t)HD_;
#pragma unroll
        for (int it = 0; it < 8; it++, r += 8) {
            float4 v = *(const float4*)(qp + (size_t)r * DIM_ + d4);
            float vv[4] = {v.x * scale, v.y * scale, v.z * scale, v.w * scale};
#pragma unroll
            for (int cc = 0; cc < 4; cc++) {
                int c = (cc + tid) & 3;
                Qs[(d4 + c) * TSTR + r] = vv[c];
            }
        }
    }

    float O[4][8];
#pragma unroll
    for (int i = 0; i < 4; i++)
#pragma unroll
        for (int j = 0; j < 8; j++) O[i][j] = 0.f;

    const float* kb_base = kbuf + (size_t)b * T_ * HD_;
    const float* vb_base = vbuf + (size_t)b * T_ * HD_;

    for (int kb = 0; kb <= qb; kb++) {
        int k0 = kb * BKV;
        __syncthreads();
        {
            int r = tid >> 5;
            int d4 = (tid & 31) << 2;
#pragma unroll
            for (int it = 0; it < 8; it++, r += 8) {
                float4 kv = *(const float4*)(kb_base + (size_t)(k0 + r) * HD_ + d4);
                float kk[4] = {kv.x, kv.y, kv.z, kv.w};
#pragma unroll
                for (int cc = 0; cc < 4; cc++) {
                    int c = (cc + tid) & 3;
                    Ks[(d4 + c) * TSTR + r] = kk[c];
                }
                float4 vv = *(const float4*)(vb_base + (size_t)(k0 + r) * HD_ + d4);
                *(float4*)&Vs[r * HD_ + d4] = vv;
            }
        }
        __syncthreads();

        float s[4][4];
#pragma unroll
        for (int i = 0; i < 4; i++)
#pragma unroll
            for (int j = 0; j < 4; j++) s[i][j] = 0.f;

#pragma unroll 4
        for (int d = 0; d < HD_; d++) {
            float4 a  = *(const float4*)&Qs[d * TSTR + ty * 4];
            float4 bb = *(const float4*)&Ks[d * TSTR + tx * 4];
            float av[4] = {a.x, a.y, a.z, a.w};
            float bv[4] = {bb.x, bb.y, bb.z, bb.w};
#pragma unroll
            for (int i = 0; i < 4; i++)
#pragma unroll
                for (int j = 0; j < 4; j++)
                    s[i][j] = fmaf(av[i], bv[j], s[i][j]);
        }

        if (kb == qb) {
#pragma unroll
            for (int i = 0; i < 4; i++)
#pragma unroll
                for (int j = 0; j < 4; j++)
                    if (ty * 4 + i < tx * 4 + j) s[i][j] = -1e30f;
        }

#pragma unroll
        for (int i = 0; i < 4; i++) {
            float mx = fmaxf(fmaxf(s[i][0], s[i][1]), fmaxf(s[i][2], s[i][3]));
            pmax[(ty * 4 + i) * MSTR + tx] = mx;
        }
        __syncthreads();

        if (tid < BQ) {
            float mt = -INFINITY;
#pragma unroll
            for (int t = 0; t < 16; t++) mt = fmaxf(mt, pmax[tid * MSTR + t]);
            float mo = rowm[tid];
            float mn = fmaxf(mo, mt);
            rowm[tid] = mn;
            rowa[tid] = __expf(mo - mn);
        }
        __syncthreads();

#pragma unroll
        for (int i = 0; i < 4; i++) {
            float mn = rowm[ty * 4 + i];
            float p0 = __expf(s[i][0] - mn);
            float p1 = __expf(s[i][1] - mn);
            float p2 = __expf(s[i][2] - mn);
            float p3 = __expf(s[i][3] - mn);
            *(float4*)&Ps[(ty * 4 + i) * PSTR + tx * 4] = make_float4(p0, p1, p2, p3);
            psum[(ty * 4 + i) * MSTR + tx] = p0 + p1 + p2 + p3;
        }
        __syncthreads();

        if (tid < BQ) {
            float sum = 0.f;
#pragma unroll
            for (int t = 0; t < 16; t++) sum += psum[tid * MSTR + t];
            rowl[tid] = rowl[tid] * rowa[tid] + sum;
        }

#pragma unroll
        for (int i = 0; i < 4; i++) {
            float al = rowa[ty * 4 + i];
#pragma unroll
            for (int j = 0; j < 8; j++) O[i][j] *= al;
        }
#pragma unroll 2
        for (int k = 0; k < BKV; k++) {
            float p[4];
#pragma unroll
            for (int i = 0; i < 4; i++) p[i] = Ps[(ty * 4 + i) * PSTR + k];
            float4 v0 = *(const float4*)&Vs[k * HD_ + tx * 8];
            float4 v1 = *(const float4*)&Vs[k * HD_ + tx * 8 + 4];
            float vv[8] = {v0.x, v0.y, v0.z, v0.w, v1.x, v1.y, v1.z, v1.w};
#pragma unroll
            for (int i = 0; i < 4; i++)
#pragma unroll
                for (int j = 0; j < 8; j++)
                    O[i][j] = fmaf(p[i], vv[j], O[i][j]);
        }
    }
    __syncthreads();

#pragma unroll
    for (int i = 0; i < 4; i++) {
        float inv = 1.f / rowl[ty * 4 + i];
        float* op = g_attn + (((size_t)b * T_ + q0 + ty * 4 + i) * H_ + h) * (size_t)HD_ + tx * 8;
        *(float4*)op       = make_float4(O[i][0] * inv, O[i][1] * inv, O[i][2] * inv, O[i][3] * inv);
        *(float4*)(op + 4) = make_float4(O[i][4] * inv, O[i][5] * inv, O[i][6] * inv, O[i][7] * inv);
    }
}

static const int FLASH_SMEM = (HD_ * TSTR * 2 + BKV * HD_ + BQ * PSTR + BQ * MSTR * 2 + 3 * BQ) * 4;

// ---------------------------------------------------------------------------
extern "C" void kernel_launch(void* const* d_in, const int* in_sizes, int n_in,
                              void* d_out, int out_size)
{
    const float* x  = (const float*)d_in[0];
    const float* Wq = (const float*)d_in[1];
    const float* Wk = (const float*)d_in[2];
    const float* Wv = (const float*)d_in[3];
    const float* Wo = (const float*)d_in[4];

    float* out = (float*)d_out;                       // [B,T,DIM]
    float* pk  = out + (size_t)B_ * T_ * DIM_;        // present_k [B,1,T,HD]
    float* pv  = pk + (size_t)B_ * T_ * HD_;          // present_v [B,1,T,HD]

    cudaFuncSetAttribute(flash_attn, cudaFuncAttributeMaxDynamicSharedMemorySize, FLASH_SMEM);

    dim3 blk(256);
    // Q = x @ Wq  -> g_q
    tgemm<<<dim3(DIM_ / 128, (B_ * T_) / 128), blk>>>(x, Wq, nullptr, B_ * T_, DIM_, DIM_, 0, 1);
    // K = x @ Wk -> present_k ; V = x @ Wv -> present_v
    tgemm<<<dim3(1, (B_ * T_) / 128), blk>>>(x, Wk, pk, B_ * T_, HD_, DIM_, 0, 0);
    tgemm<<<dim3(1, (B_ * T_) / 128), blk>>>(x, Wv, pv, B_ * T_, HD_, DIM_, 0, 0);
    // RoPE in place
    rope_q_kernel<<<(B_ * T_ * H_ * 64) / 256, blk>>>();
    rope_k_kernel<<<(B_ * T_ * 64) / 256, blk>>>(pk);
    // Attention -> g_attn
    flash_attn<<<dim3(T_ / BQ, B_ * H_), blk, FLASH_SMEM>>>(pk, pv);
    // out = attn @ Wo
    tgemm<<<dim3(DIM_ / 128, (B_ * T_) / 128), blk>>>(nullptr, Wo, out, B_ * T_, DIM_, DIM_, 1, 0);
}